// round 7
// baseline (speedup 1.0000x reference)
#include <cuda_runtime.h>

// Temporal-blocked persistent solver, R7: packed-f32x2 conservative state.
//  - NT=320, PPT=12 as 6 f32x2 pairs (cells j and j+6) -> LBUF=3840,
//    HALO=128/side, TILE=3584, GRID=296, stride=3543 (perfect balance, occ 2).
//  - State R=rho, Ms=C1*mom packed; derived Vs=C1*v, FPs=C1^2*(rho v^2+P).
//  - Pass 2 entirely packed (10 f32x2 ops / pair). Pass 1: scalar MUFU per
//    half, one unpack + two packs per pair.
//  - Seam pairs: prev(pair0)=(nbrLast, pair5.lo), next(pair5)=(pair0.hi, nbrFirst).
//  - float4 edge exchange, double-buffered -> ONE __syncthreads per step.
//  - No clamps in hot loop; halo garbage advances 1 cell/step, never reaches output.

#define NT    320
#define PPT   12
#define PAIRS 6
#define LBUF  (NT * PPT)            // 3840
#define HALO  128
#define TILE  (LBUF - 2 * HALO)     // 3584
#define GRID  296

typedef unsigned long long ull;

__device__ __forceinline__ ull pk(float a, float b) {
    ull r; asm("mov.b64 %0, {%1,%2};" : "=l"(r) : "f"(a), "f"(b)); return r;
}
__device__ __forceinline__ void upk(float& a, float& b, ull v) {
    asm("mov.b64 {%0,%1}, %2;" : "=f"(a), "=f"(b) : "l"(v));
}
__device__ __forceinline__ ull add2(ull a, ull b) {
    ull r; asm("add.rn.f32x2 %0, %1, %2;" : "=l"(r) : "l"(a), "l"(b)); return r;
}
__device__ __forceinline__ ull mul2(ull a, ull b) {
    ull r; asm("mul.rn.f32x2 %0, %1, %2;" : "=l"(r) : "l"(a), "l"(b)); return r;
}
__device__ __forceinline__ ull fma2(ull a, ull b, ull c) {
    ull r; asm("fma.rn.f32x2 %0, %1, %2, %3;" : "=l"(r) : "l"(a), "l"(b), "l"(c)); return r;
}
__device__ __forceinline__ float xlg2(float x) {
    float r; asm("lg2.approx.f32 %0, %1;" : "=f"(r) : "f"(x)); return r;
}
__device__ __forceinline__ float xex2(float x) {
    float r; asm("ex2.approx.f32 %0, %1;" : "=f"(r) : "f"(x)); return r;
}
__device__ __forceinline__ float xrcp(float x) {
    float r; asm("rcp.approx.f32 %0, %1;" : "=f"(r) : "f"(x)); return r;
}

__global__ __launch_bounds__(NT, 2)
void obf_solver_kernel(const float* __restrict__ rho0,
                       const float* __restrict__ v0,
                       const int*   __restrict__ n_steps_ptr,
                       float*       __restrict__ out,
                       int N, int stride)
{
    // Double-buffered float4 edge exchange: [parity][0=Last/1=First][thread]
    // Last  = cell c+11 of this thread : {R, Ms, Vs, FPs}
    // First = cell c    of this thread : {R, Ms, Vs, FPs}
    __shared__ float4 S[2][2][NT];

    const int t = threadIdx.x;
    const int b = blockIdx.x;
    const int base = b * stride - HALO + t * PPT;

    const float C1    = 0.005f;                 // DT/(2*DX)
    const float LGC12 = -15.287712379549449f;   // lg2(C1^2)
    const float INVC1 = 200.0f;

    ull R[PAIRS], Ms[PAIRS], Vs[PAIRS], FPs[PAIRS];

    // ---- load initial state (periodic wrap); pairs (cell j, cell j+6) ----
    #pragma unroll
    for (int j = 0; j < PAIRS; ++j) {
        int gA = base + j + N;
        if (gA >= N) gA -= N; if (gA >= N) gA -= N;
        int gB = base + j + PAIRS + N;
        if (gB >= N) gB -= N; if (gB >= N) gB -= N;
        float rA = rho0[gA], vA = v0[gA];
        float rB = rho0[gB], vB = v0[gB];
        R[j]  = pk(rA, rB);
        Ms[j] = pk((C1 * rA) * vA, (C1 * rB) * vB);
    }

    const int n_steps = *n_steps_ptr;

    const ull HALFP = pk(0.5f, 0.5f);
    const ull NEG1  = pk(-1.0f, -1.0f);
    const ull NEG2  = pk(-2.0f, -2.0f);
    const ull C2P   = pk(0.01f, 0.01f);         // DT*MU/DX^2

    const int lt = (t == 0)      ? 0      : t - 1;
    const int rt = (t == NT - 1) ? NT - 1 : t + 1;

    int p = 0;
    for (int s = 0; s < n_steps; ++s) {
        // ---- pass 1: Vs = C1*v, FPs = C1^2*(rho v^2 + P), packed ----
        #pragma unroll
        for (int j = 0; j < PAIRS; ++j) {
            float ra, rb; upk(ra, rb, R[j]);
            float ia = xrcp(ra), ib = xrcp(rb);
            Vs[j] = mul2(Ms[j], pk(ia, ib));                    // C1 * v
            float Pa = xex2(fmaf(1.4f, xlg2(ra), LGC12));       // C1^2 * rho^1.4
            float Pb = xex2(fmaf(1.4f, xlg2(rb), LGC12));
            FPs[j] = fma2(Ms[j], Vs[j], pk(Pa, Pb));
        }

        // ---- seam unpacks + edge publish ----
        float R0lo, R0hi, R5lo, R5hi;   upk(R0lo, R0hi, R[0]);   upk(R5lo, R5hi, R[PAIRS-1]);
        float M0lo, M0hi, M5lo, M5hi;   upk(M0lo, M0hi, Ms[0]);  upk(M5lo, M5hi, Ms[PAIRS-1]);
        float V0lo, V0hi, V5lo, V5hi;   upk(V0lo, V0hi, Vs[0]);  upk(V5lo, V5hi, Vs[PAIRS-1]);
        float F0lo, F0hi, F5lo, F5hi;   upk(F0lo, F0hi, FPs[0]); upk(F5lo, F5hi, FPs[PAIRS-1]);

        S[p][0][t] = make_float4(R5hi, M5hi, V5hi, F5hi);   // last cell (c+11)
        S[p][1][t] = make_float4(R0lo, M0lo, V0lo, F0lo);   // first cell (c)
        __syncthreads();

        float4 eL = S[p][0][lt];    // neighbor's last cell  = cell c-1
        float4 eR = S[p][1][rt];    // neighbor's first cell = cell c+12
        p ^= 1;                     // next step uses other buffer

        // prev of pair0 = (c-1, c+5) ; next of pair5 = (c+6, c+12)
        ull prevR = pk(eL.x, R5lo), prevM = pk(eL.y, M5lo);
        ull prevV = pk(eL.z, V5lo), prevF = pk(eL.w, F5lo);
        ull nextR = pk(R0hi, eR.x), nextM = pk(M0hi, eR.y);
        ull nextV = pk(V0hi, eR.z), nextF = pk(F0hi, eR.w);

        // ---- pass 2: Lax-Friedrichs update, fully packed ----
        ull pR = prevR, pM = prevM, pV = prevV, pF = prevF;
        #pragma unroll
        for (int j = 0; j < PAIRS; ++j) {
            const bool last = (j == PAIRS - 1);
            ull nR = last ? nextR : R[j + 1];
            ull nM = last ? nextM : Ms[j + 1];
            ull nV = last ? nextV : Vs[j + 1];
            ull nF = last ? nextF : FPs[j + 1];

            ull dM   = fma2(nM, NEG1, pM);          // pM - nM
            ull su   = add2(nR, pR);
            ull rnew = fma2(HALFP, su, dM);         // 0.5*(nR+pR) - (nM-pM)

            ull vsum = add2(nV, pV);
            ull visc = fma2(NEG2, Vs[j], vsum);     // C1*(vn+vp-2v)

            ull dF   = fma2(nF, NEG1, pF);          // pF - nF
            ull msum = add2(nM, pM);
            ull m0   = fma2(HALFP, msum, dF);
            ull cr   = mul2(C2P, R[j]);
            ull mnew = fma2(cr, visc, m0);

            pR = R[j]; pM = Ms[j]; pV = Vs[j]; pF = FPs[j];
            R[j] = rnew; Ms[j] = mnew;
        }
    }

    // ---- store valid interior: rho and v = (Ms/C1)/max(rho,1e-10) ----
    float* orho = out;
    float* ov   = out + N;
    #pragma unroll
    for (int j = 0; j < PAIRS; ++j) {
        float ra, rb, ma, mb;
        upk(ra, rb, R[j]); upk(ma, mb, Ms[j]);
        int lA = t * PPT + j;
        if (lA >= HALO && lA < LBUF - HALO) {
            int g = b * stride + (lA - HALO);
            if (g >= N) g -= N;
            orho[g] = ra;
            ov[g]   = (INVC1 * ma) * xrcp(fmaxf(ra, 1e-10f));
        }
        int lB = lA + PAIRS;
        if (lB >= HALO && lB < LBUF - HALO) {
            int g = b * stride + (lB - HALO);
            if (g >= N) g -= N;
            orho[g] = rb;
            ov[g]   = (INVC1 * mb) * xrcp(fmaxf(rb, 1e-10f));
        }
    }
}

extern "C" void kernel_launch(void* const* d_in, const int* in_sizes, int n_in,
                              void* d_out, int out_size)
{
    const float* rho0   = (const float*)d_in[0];
    const float* v0     = (const float*)d_in[1];
    const int*   nsteps = (const int*)d_in[2];
    float*       out    = (float*)d_out;

    const int N = in_sizes[0];
    int grid = GRID;
    if ((long long)grid * TILE < N)                 // safety for other shapes
        grid = (N + TILE - 1) / TILE;
    int stride = (N + grid - 1) / grid;             // 3543 <= TILE here

    obf_solver_kernel<<<grid, NT>>>(rho0, v0, nsteps, out, N, stride);
}

// round 8
// speedup vs baseline: 1.0789x; 1.0789x over previous
#include <cuda_runtime.h>

// Temporal-blocked persistent solver, R8: R5 math + static-parity double
// buffering + float4 edge exchange.
//  - NT=256, PPT=15 -> LBUF=3840, HALO=128/side, TILE=3584, GRID=296,
//    stride=3543 (perfect balance, occ 2).
//  - C1-scaled conservative state: R=rho, Ms=C1*mom; derived Vs=C1*v,
//    FPs=C1^2*(rho v^2+P); C1^2 folded into the pow constant.
//  - Time loop unrolled by 2: step A publishes edges in S0, step B in S1 —
//    compile-time buffer selection => immediate smem offsets, no parity math.
//  - Edge exchange as ONE float4 store/load per end (was 4 scalars).
//  - ONE __syncthreads per step (read of buffer X at step s precedes the
//    next write of X at step s+2).
//  - No clamps in hot loop; halo garbage advances 1 cell/step, never reaches
//    the stored interior.

#define NT   256
#define PPT  15
#define LBUF (NT * PPT)            // 3840
#define HALO 128
#define TILE (LBUF - 2 * HALO)     // 3584
#define GRID 296

__device__ __forceinline__ float xlg2(float x) {
    float r; asm("lg2.approx.f32 %0, %1;" : "=f"(r) : "f"(x)); return r;
}
__device__ __forceinline__ float xex2(float x) {
    float r; asm("ex2.approx.f32 %0, %1;" : "=f"(r) : "f"(x)); return r;
}
__device__ __forceinline__ float xrcp(float x) {
    float r; asm("rcp.approx.f32 %0, %1;" : "=f"(r) : "f"(x)); return r;
}

// One Lax-Friedrichs step. SL/SF are this step's edge buffers (compile-time
// distinct per parity thanks to the unrolled caller).
__device__ __forceinline__ void lxf_step(float R[PPT], float Ms[PPT],
                                         float4* __restrict__ SL,
                                         float4* __restrict__ SF,
                                         int t, int lt, int rt)
{
    const float LGC12 = -15.287712379549449f;   // lg2(C1^2), C1 = DT/(2*DX)
    float Vs[PPT], FPs[PPT];

    // pass 1: Vs = C1*v, FPs = C1^2*(rho v^2 + P)
    #pragma unroll
    for (int j = 0; j < PPT; ++j) {
        float rinv = xrcp(R[j]);
        Vs[j] = Ms[j] * rinv;
        float Pp = xex2(fmaf(1.4f, xlg2(R[j]), LGC12));
        FPs[j] = fmaf(Ms[j], Vs[j], Pp);
    }

    // edge publish: one float4 per end
    SL[t] = make_float4(R[PPT - 1], Ms[PPT - 1], Vs[PPT - 1], FPs[PPT - 1]);
    SF[t] = make_float4(R[0],       Ms[0],       Vs[0],       FPs[0]);
    __syncthreads();

    float4 eL = SL[lt];   // neighbor's last cell  (my cell -1)
    float4 eR = SF[rt];   // neighbor's first cell (my cell +PPT)

    // pass 2: update on scaled (R, Ms)
    float pR = eL.x, pM = eL.y, pV = eL.z, pF = eL.w;
    #pragma unroll
    for (int j = 0; j < PPT; ++j) {
        const bool last = (j == PPT - 1);           // compile-time
        float nR = last ? eR.x : R[j + 1];
        float nM = last ? eR.y : Ms[j + 1];
        float nV = last ? eR.z : Vs[j + 1];
        float nF = last ? eR.w : FPs[j + 1];

        float dM    = nM - pM;
        float rnew  = fmaf(0.5f, nR + pR, -dM);

        float visc  = fmaf(-2.0f, Vs[j], nV + pV);  // C1*(vn+vp-2v)

        float dF    = nF - pF;
        float m0    = fmaf(0.5f, nM + pM, -dF);
        float msnew = fmaf(0.01f * R[j], visc, m0); // C2 = DT*MU/DX^2

        pR = R[j]; pM = Ms[j]; pV = Vs[j]; pF = FPs[j];
        R[j] = rnew; Ms[j] = msnew;
    }
}

__global__ __launch_bounds__(NT, 2)
void obf_solver_kernel(const float* __restrict__ rho0,
                       const float* __restrict__ v0,
                       const int*   __restrict__ n_steps_ptr,
                       float*       __restrict__ out,
                       int N, int stride)
{
    // Two statically-selected edge buffers: [0]=Last-cell, [1]=First-cell.
    __shared__ float4 S0[2][NT];
    __shared__ float4 S1[2][NT];

    const int t = threadIdx.x;
    const int b = blockIdx.x;
    const int base = b * stride - HALO + t * PPT;

    const float C1    = 0.005f;
    const float INVC1 = 200.0f;

    float R[PPT], Ms[PPT];

    // ---- load initial state (periodic wrap); Ms = C1 * rho * v ----
    #pragma unroll
    for (int j = 0; j < PPT; ++j) {
        int g = base + j + N;
        if (g >= N) g -= N;
        if (g >= N) g -= N;
        float r = rho0[g];
        float v = v0[g];
        R[j]  = r;
        Ms[j] = (C1 * r) * v;
    }

    const int n_steps = *n_steps_ptr;

    const int lt = (t == 0)      ? 0      : t - 1;
    const int rt = (t == NT - 1) ? NT - 1 : t + 1;

    int s = 0;
    for (; s + 1 < n_steps; s += 2) {
        lxf_step(R, Ms, S0[0], S0[1], t, lt, rt);   // parity 0
        lxf_step(R, Ms, S1[0], S1[1], t, lt, rt);   // parity 1
    }
    if (s < n_steps) {
        lxf_step(R, Ms, S0[0], S0[1], t, lt, rt);
    }

    // ---- store valid interior: rho and v = (Ms/C1)/max(rho,1e-10) ----
    float* orho = out;
    float* ov   = out + N;
    #pragma unroll
    for (int j = 0; j < PPT; ++j) {
        int l = t * PPT + j;                 // local index in [0, LBUF)
        if (l >= HALO && l < LBUF - HALO) {
            int g = b * stride + (l - HALO);
            if (g >= N) g -= N;
            orho[g] = R[j];
            ov[g]   = (INVC1 * Ms[j]) * xrcp(fmaxf(R[j], 1e-10f));
        }
    }
}

extern "C" void kernel_launch(void* const* d_in, const int* in_sizes, int n_in,
                              void* d_out, int out_size)
{
    const float* rho0   = (const float*)d_in[0];
    const float* v0     = (const float*)d_in[1];
    const int*   nsteps = (const int*)d_in[2];
    float*       out    = (float*)d_out;

    const int N = in_sizes[0];
    int grid = GRID;
    if ((long long)grid * TILE < N)                 // safety for other shapes
        grid = (N + TILE - 1) / TILE;
    int stride = (N + grid - 1) / grid;             // 3543 <= TILE here

    obf_solver_kernel<<<grid, NT>>>(rho0, v0, nsteps, out, N, stride);
}